// round 10
// baseline (speedup 1.0000x reference)
#include <cuda_runtime.h>
#include <cuda_bf16.h>
#include <math.h>

#define BB 16

// ---------------- scratch ----------------
__device__ float  g_h0[BB*4096*32];
__device__ float  g_h1[BB*1024*64];
__device__ float  g_h2[BB*256*128];
__device__ float  g_h3[BB*64*256];
__device__ float  g_h4[BB*16*512];
__device__ float  g_p1[BB*1024*3];
__device__ float  g_p2[BB*256*3];
__device__ float  g_p3[BB*64*3];
__device__ float  g_p4[BB*16*3];
__device__ int    g_idx[BB*1024];
__device__ int    g_nidx[BB*(1024+256+64+16)*16];
__device__ float  g_gmax[BB*1024*64];
__device__ double g_sum[5][512], g_sqs[5][512];
__device__ float  g_z[BB*512];
__device__ float  g_t1[BB*256];
__device__ float  g_t2[BB*128];

// ---------------- zero all BN stats ----------------
__global__ void zero_all_kernel()
{
    int i = blockIdx.x * blockDim.x + threadIdx.x;
    if (i < 5*512) { (&g_sum[0][0])[i] = 0.0; (&g_sqs[0][0])[i] = 0.0; }
}

// ---------------- stage 0 linear ----------------
__global__ void lin0_kernel(const float* __restrict__ x, const float* __restrict__ W1,
                            float* __restrict__ h)
{
    int gid = blockIdx.x * blockDim.x + threadIdx.x;
    if (gid >= BB*4096*32) return;
    int d = gid & 31, r = gid >> 5;
    float v =        __ldg(x + r*3 + 0) * __ldg(W1 + d);
    v = fmaf(__ldg(x + r*3 + 1), __ldg(W1 + 32 + d), v);
    v = fmaf(__ldg(x + r*3 + 2), __ldg(W1 + 64 + d), v);
    h[gid] = v;
}

// ---------------- BN statistics (stage 0 only) ----------------
__global__ void stats_kernel(const float* __restrict__ y, int nrows, int C,
                             double* __restrict__ sumr, double* __restrict__ sqsr)
{
    int c  = threadIdx.x;
    int r0 = blockIdx.x * blockDim.y + threadIdx.y;
    int stride = gridDim.x * blockDim.y;
    double s = 0.0, q = 0.0;
    for (int r = r0; r < nrows; r += stride) {
        float v = y[(long long)r * C + c];
        s += (double)v;
        q += (double)v * (double)v;
    }
    atomicAdd(&sumr[c], s);
    atomicAdd(&sqsr[c], q);
}

__global__ void bnrelu32_kernel(float* __restrict__ h, int total,
                                const double* __restrict__ sumr, const double* __restrict__ sqsr,
                                const float* __restrict__ g, const float* __restrict__ b,
                                double inv_n)
{
    __shared__ float ssc[32], ssh[32];
    if (threadIdx.x < 32) {
        int c = threadIdx.x;
        double m = sumr[c] * inv_n;
        double v = sqsr[c] * inv_n - m * m;
        float rstd = (float)rsqrt(v + 1e-5);
        float sc = __ldg(g + c) * rstd;
        ssc[c] = sc; ssh[c] = __ldg(b + c) - (float)m * sc;
    }
    __syncthreads();
    int gid = blockIdx.x * blockDim.x + threadIdx.x;
    if (gid >= total) return;
    int c = gid & 31;
    float v = fmaf(h[gid], ssc[c], ssh[c]);
    h[gid] = v > 0.f ? v : 0.f;
}

__global__ void bnapply_kernel(const float* __restrict__ gmax, float* __restrict__ hout,
                               int total, int C,
                               const double* __restrict__ sumr, const double* __restrict__ sqsr,
                               const float* __restrict__ g, const float* __restrict__ b,
                               double inv_n)
{
    __shared__ float ssc[512], ssh[512];
    for (int c = threadIdx.x; c < C; c += blockDim.x) {
        double m = sumr[c] * inv_n;
        double v = sqsr[c] * inv_n - m * m;
        float rstd = (float)rsqrt(v + 1e-5);
        float sc = __ldg(g + c) * rstd;
        ssc[c] = sc; ssh[c] = __ldg(b + c) - (float)m * sc;
    }
    __syncthreads();
    int gid = blockIdx.x * blockDim.x + threadIdx.x;
    if (gid >= total) return;
    int c = gid & (C - 1);
    float v = fmaf(gmax[gid], ssc[c], ssh[c]);
    hout[gid] = v > 0.f ? v : 0.f;
}

// ---------------- FPS v3: lean scan + smem coord broadcast + direct p_out ----------------
template<int N, int M, int T>
__global__ void __launch_bounds__(T) fps3_kernel(const float* __restrict__ p,
                                                 int* __restrict__ out_idx,
                                                 float* __restrict__ p_out)
{
    constexpr int P = N / T;
    constexpr int NW = T / 32;
    int b = blockIdx.x;
    const float* pb = p + (long long)b * N * 3;
    float* po = p_out + (long long)b * M * 3;
    int tid = threadIdx.x, lane = tid & 31, w = tid >> 5;

    float px[P], py[P], pz[P], md[P];
#pragma unroll
    for (int i = 0; i < P; i++) {
        int n = tid + i * T;
        px[i] = __ldg(pb + 3*n); py[i] = __ldg(pb + 3*n + 1); pz[i] = __ldg(pb + 3*n + 2);
        md[i] = 3.4e38f;
    }

    __shared__ unsigned sv[2][NW];
    __shared__ unsigned si[2][NW];
    __shared__ float swc[2][NW][3];
    int last = 0;
    float lx = __ldg(pb + 0), ly = __ldg(pb + 1), lz = __ldg(pb + 2);

    for (int m = 0; m < M; m++) {
        if (tid == 0) {
            out_idx[b*M + m] = last;
            po[3*m] = lx; po[3*m+1] = ly; po[3*m+2] = lz;
        }
        // 1) min-dist update only (lean: 7 instr/pt)
#pragma unroll
        for (int i = 0; i < P; i++) {
            float dx = px[i] - lx, dy = py[i] - ly, dz = pz[i] - lz;
            float d = fmaf(dx, dx, fmaf(dy, dy, dz*dz));
            md[i] = fminf(md[i], d);
        }
        // 2) per-thread argmax: fmax tree + descending equality scan (lowest i wins ties)
        float bestv = md[0];
#pragma unroll
        for (int i = 1; i < P; i++) bestv = fmaxf(bestv, md[i]);
        unsigned besti = 0;
#pragma unroll
        for (int i = P-1; i >= 0; --i) if (md[i] == bestv) besti = (unsigned)(tid + i*T);

        unsigned fb = __float_as_uint(bestv);
        unsigned wmax = __reduce_max_sync(0xffffffffu, fb);
        unsigned cand = (fb == wmax) ? besti : 0xffffffffu;
        unsigned widx = __reduce_min_sync(0xffffffffu, cand);
        int buf = m & 1;
        if (lane == 0) { sv[buf][w] = wmax; si[buf][w] = widx; }
        if (cand == widx) {           // unique winner lane of this warp
#pragma unroll
            for (int i = 0; i < P; i++)
                if (widx == (unsigned)(tid + i*T)) {
                    swc[buf][w][0] = px[i]; swc[buf][w][1] = py[i]; swc[buf][w][2] = pz[i];
                }
        }
        __syncthreads();
        unsigned vv = (lane < NW) ? sv[buf][lane] : 0u;
        unsigned ii = (lane < NW) ? si[buf][lane] : 0xffffffffu;
        unsigned m2 = __reduce_max_sync(0xffffffffu, vv);
        unsigned c2 = (vv == m2) ? ii : 0xffffffffu;
        unsigned lst = __reduce_min_sync(0xffffffffu, c2);
        last = (int)lst;
        unsigned bal = __ballot_sync(0xffffffffu, vv == m2 && ii == lst);
        int ws = __ffs(bal) - 1;
        lx = swc[buf][ws][0]; ly = swc[buf][ws][1]; lz = swc[buf][ws][2];
    }
}

// ---------------- warp-per-query kNN ----------------
template<int N, int WPB>
__global__ void __launch_bounds__(WPB*32) knn_warp_kernel(const float* __restrict__ p,
                                                          const float* __restrict__ q,
                                                          int M, int* __restrict__ nidx)
{
    extern __shared__ float sm[];
    float* sx = sm; float* sy = sm + N; float* sz = sm + 2*N;
    int tid = threadIdx.x, lane = tid & 31, w = tid >> 5;
    int bpb = M / WPB;
    int b  = blockIdx.x / bpb;
    int q0 = (blockIdx.x % bpb) * WPB;
    const float* pb = p + (long long)b * N * 3;
    for (int i = tid; i < N; i += WPB*32) {
        sx[i] = pb[3*i]; sy[i] = pb[3*i+1]; sz[i] = pb[3*i+2];
    }
    __syncthreads();

    int qi = q0 + w;
    const float* qp = q + ((long long)b * M + qi) * 3;
    float qx = qp[0], qy = qp[1], qz = qp[2];

    float kd[16]; int ki[16];    // replicated + sorted across all lanes
#pragma unroll
    for (int i = 0; i < 16; i++) { kd[i] = 3.4e38f; ki[i] = 0; }

    for (int n0 = 0; n0 < N; n0 += 32) {
        int n = n0 + lane;
        float dx = sx[n] - qx, dy = sy[n] - qy, dz = sz[n] - qz;
        float d = fmaf(dx, dx, fmaf(dy, dy, dz*dz));
        unsigned mask = __ballot_sync(0xffffffffu, d < kd[15]);
        while (mask) {
            int src = __ffs(mask) - 1;
            mask &= mask - 1;
            float dd = __shfl_sync(0xffffffffu, d, src);
            if (dd < kd[15]) {       // uniform recheck (kd[15] may have shrunk)
                kd[15] = dd; ki[15] = n0 + src;
#pragma unroll
                for (int j = 15; j > 0; --j) {
                    if (kd[j] < kd[j-1]) {
                        float td = kd[j]; kd[j] = kd[j-1]; kd[j-1] = td;
                        int   ti = ki[j]; ki[j] = ki[j-1]; ki[j-1] = ti;
                    }
                }
            }
        }
    }
    if (lane == 0) {
        int base = ((long long)b * M + qi) * 16;
#pragma unroll
        for (int j = 0; j < 16; j++) nidx[base + j] = ki[j];
    }
}

// ---------------- fused GEMM ----------------
__global__ void __launch_bounds__(256) gemmF_kernel(
    const float* __restrict__ p_in, const float* __restrict__ h_in,
    const float* __restrict__ newp, const int* __restrict__ nidx,
    const float* __restrict__ W, float* __restrict__ gmax,
    int N, int M, int Cin, int COUT,
    double* __restrict__ sumr, double* __restrict__ sqsr)
{
    int CK = Cin + 3;
    __shared__ float As[16][68];
    __shared__ float Bs[16][68];
    __shared__ int sH[64], sP[64], sQ[64];
    int t = threadIdx.x;
    int row0 = blockIdx.x * 64;
    int col0 = blockIdx.y * 64;
    int tx = t & 15, ty = t >> 4;

    if (t < 64) {
        int r  = row0 + t;
        int n  = nidx[r];
        int bm = r >> 4;
        int b  = bm / M;
        sH[t] = (b * N + n) * Cin;
        sP[t] = (b * N + n) * 3;
        sQ[t] = bm * 3;
    }
    __syncthreads();

    float acc[4][4];
#pragma unroll
    for (int i = 0; i < 4; i++)
#pragma unroll
        for (int j = 0; j < 4; j++) acc[i][j] = 0.f;

    for (int k0 = 0; k0 < CK; k0 += 16) {
#pragma unroll
        for (int j = 0; j < 4; j++) {
            int lin = t + j * 256;
            int i = lin >> 4, kk = lin & 15;
            int c = k0 + kk;
            float v = 0.f;
            if (c < CK) {
                if (c < 3) v = __ldg(p_in + sP[i] + c) - __ldg(newp + sQ[i] + c);
                else       v = __ldg(h_in + sH[i] + c - 3);
            }
            As[kk][i] = v;
        }
#pragma unroll
        for (int j = 0; j < 4; j++) {
            int lin = t + j * 256;
            int kk = lin >> 6, cc = lin & 63;
            Bs[kk][cc] = (k0 + kk < CK) ? __ldg(W + (long long)(k0 + kk) * COUT + col0 + cc) : 0.f;
        }
        __syncthreads();
#pragma unroll
        for (int kk = 0; kk < 16; kk++) {
            float a0 = As[kk][ty*4+0], a1 = As[kk][ty*4+1], a2 = As[kk][ty*4+2], a3 = As[kk][ty*4+3];
            float b0 = Bs[kk][tx*4+0], b1 = Bs[kk][tx*4+1], b2 = Bs[kk][tx*4+2], b3 = Bs[kk][tx*4+3];
            acc[0][0]=fmaf(a0,b0,acc[0][0]); acc[0][1]=fmaf(a0,b1,acc[0][1]);
            acc[0][2]=fmaf(a0,b2,acc[0][2]); acc[0][3]=fmaf(a0,b3,acc[0][3]);
            acc[1][0]=fmaf(a1,b0,acc[1][0]); acc[1][1]=fmaf(a1,b1,acc[1][1]);
            acc[1][2]=fmaf(a1,b2,acc[1][2]); acc[1][3]=fmaf(a1,b3,acc[1][3]);
            acc[2][0]=fmaf(a2,b0,acc[2][0]); acc[2][1]=fmaf(a2,b1,acc[2][1]);
            acc[2][2]=fmaf(a2,b2,acc[2][2]); acc[2][3]=fmaf(a2,b3,acc[2][3]);
            acc[3][0]=fmaf(a3,b0,acc[3][0]); acc[3][1]=fmaf(a3,b1,acc[3][1]);
            acc[3][2]=fmaf(a3,b2,acc[3][2]); acc[3][3]=fmaf(a3,b3,acc[3][3]);
        }
        __syncthreads();
    }

    float cs[4], cq[4], cm[4];
#pragma unroll
    for (int j = 0; j < 4; j++) {
        cs[j] = acc[0][j] + acc[1][j] + acc[2][j] + acc[3][j];
        cq[j] = acc[0][j]*acc[0][j] + acc[1][j]*acc[1][j] + acc[2][j]*acc[2][j] + acc[3][j]*acc[3][j];
        cm[j] = fmaxf(fmaxf(acc[0][j], acc[1][j]), fmaxf(acc[2][j], acc[3][j]));
    }
#pragma unroll
    for (int j = 0; j < 4; j++) { As[ty][tx*4+j] = cs[j]; Bs[ty][tx*4+j] = cq[j]; }
    __syncthreads();
    if (t < 64) {
        double s = 0.0, q = 0.0;
#pragma unroll
        for (int r = 0; r < 16; r++) { s += (double)As[r][t]; q += (double)Bs[r][t]; }
        atomicAdd(&sumr[col0 + t], s);
        atomicAdd(&sqsr[col0 + t], q);
    }
    __syncthreads();
#pragma unroll
    for (int j = 0; j < 4; j++) As[ty][tx*4+j] = cm[j];
    __syncthreads();
    {
        int grp = t >> 6, col = t & 63;
        float mm = fmaxf(fmaxf(As[grp*4+0][col], As[grp*4+1][col]),
                         fmaxf(As[grp*4+2][col], As[grp*4+3][col]));
        gmax[(long long)((row0 >> 4) + grp) * COUT + col0 + col] = mm;
    }
}

// ---------------- mean pool ----------------
__global__ void mean_kernel(const float* __restrict__ h4)
{
    int gid = blockIdx.x * blockDim.x + threadIdx.x;
    if (gid >= BB * 512) return;
    int c = gid & 511, b = gid >> 9;
    float s = 0.f;
#pragma unroll
    for (int k = 0; k < 16; k++) s += h4[((long long)b * 16 + k) * 512 + c];
    g_z[gid] = s * (1.f / 16.f);
}

// ---------------- classifier head ----------------
__global__ void head_kernel(const float* __restrict__ in, const float* __restrict__ W,
                            const float* __restrict__ bias,
                            const float* __restrict__ gg, const float* __restrict__ bb,
                            float* __restrict__ outp, int Cin, int Cout, int bn_relu)
{
    __shared__ float s_in[16*512];
    int tid = threadIdx.x;
    for (int i = tid; i < 16*Cin; i += blockDim.x) s_in[i] = in[i];
    __syncthreads();

    int j = blockIdx.x * blockDim.x + tid;
    if (j >= Cout) return;
    float acc[16];
    float bs = __ldg(bias + j);
#pragma unroll
    for (int b = 0; b < 16; b++) acc[b] = bs;
    for (int c = 0; c < Cin; c++) {
        float w = __ldg(W + (long long)c * Cout + j);
#pragma unroll
        for (int b = 0; b < 16; b++) acc[b] = fmaf(s_in[b*Cin + c], w, acc[b]);
    }
    if (bn_relu) {
        float s = 0.f;
#pragma unroll
        for (int b = 0; b < 16; b++) s += acc[b];
        float m = s * (1.f/16.f);
        float v = 0.f;
#pragma unroll
        for (int b = 0; b < 16; b++) { float d = acc[b] - m; v = fmaf(d, d, v); }
        v *= (1.f/16.f);
        float sc = __ldg(gg + j) * rsqrtf(v + 1e-5f);
        float sh = __ldg(bb + j) - m * sc;
#pragma unroll
        for (int b = 0; b < 16; b++) {
            float o = fmaf(acc[b], sc, sh);
            outp[b*Cout + j] = o > 0.f ? o : 0.f;
        }
    } else {
#pragma unroll
        for (int b = 0; b < 16; b++) outp[b*Cout + j] = acc[b];
    }
}

// ---------------- host ----------------
static void run_fps(const float* p, int* idx, float* pout, int N, cudaStream_t st)
{
    if      (N == 4096) fps3_kernel<4096,1024,512><<<BB,512,0,st>>>(p, idx, pout);
    else if (N == 1024) fps3_kernel<1024, 256,512><<<BB,512,0,st>>>(p, idx, pout);
    else if (N ==  256) fps3_kernel< 256,  64,256><<<BB,256,0,st>>>(p, idx, pout);
    else                fps3_kernel<  64,  16, 64><<<BB, 64,0,st>>>(p, idx, pout);
}

static void run_knn(const float* p, const float* q, int N, int M, int* nidx, cudaStream_t st)
{
    if      (N == 4096) knn_warp_kernel<4096,8><<<BB*(M/8),256,3*4096*4,st>>>(p, q, M, nidx);
    else if (N == 1024) knn_warp_kernel<1024,8><<<BB*(M/8),256,3*1024*4,st>>>(p, q, M, nidx);
    else if (N ==  256) knn_warp_kernel< 256,8><<<BB*(M/8),256,3* 256*4,st>>>(p, q, M, nidx);
    else                knn_warp_kernel<  64,8><<<BB*(M/8),256,3*  64*4,st>>>(p, q, M, nidx);
}

extern "C" void kernel_launch(void* const* d_in, const int* in_sizes, int n_in,
                              void* d_out, int out_size)
{
    const float* x   = (const float*)d_in[0];
    const float* W1  = (const float*)d_in[1];
    const float* g1  = (const float*)d_in[2];
    const float* b1  = (const float*)d_in[3];
    const float* Ws[4]  = {(const float*)d_in[4], (const float*)d_in[7], (const float*)d_in[10], (const float*)d_in[13]};
    const float* gs[4]  = {(const float*)d_in[5], (const float*)d_in[8], (const float*)d_in[11], (const float*)d_in[14]};
    const float* bs[4]  = {(const float*)d_in[6], (const float*)d_in[9], (const float*)d_in[12], (const float*)d_in[15]};
    const float* Wc1 = (const float*)d_in[16];
    const float* bc1 = (const float*)d_in[17];
    const float* gc1 = (const float*)d_in[18];
    const float* hc1 = (const float*)d_in[19];
    const float* Wc2 = (const float*)d_in[20];
    const float* bc2 = (const float*)d_in[21];
    const float* gc2 = (const float*)d_in[22];
    const float* hc2 = (const float*)d_in[23];
    const float* Wc3 = (const float*)d_in[24];
    const float* bc3 = (const float*)d_in[25];
    float* out = (float*)d_out;

    static cudaStream_t sF = 0, sK = 0;
    static cudaEvent_t eRoot, eG[4], eK[4], eF;
    static bool inited = false;
    if (!inited) {
        cudaStreamCreateWithFlags(&sF, cudaStreamNonBlocking);
        cudaStreamCreateWithFlags(&sK, cudaStreamNonBlocking);
        cudaEventCreateWithFlags(&eRoot, cudaEventDisableTiming);
        cudaEventCreateWithFlags(&eF,    cudaEventDisableTiming);
        for (int i = 0; i < 4; i++) {
            cudaEventCreateWithFlags(&eG[i], cudaEventDisableTiming);
            cudaEventCreateWithFlags(&eK[i], cudaEventDisableTiming);
        }
        cudaFuncSetAttribute(knn_warp_kernel<4096,8>,
                             cudaFuncAttributeMaxDynamicSharedMemorySize, 3*4096*4);
        inited = true;
    }

    float *h0, *h1, *h2, *h3, *h4, *p1, *p2, *p3, *p4, *gmax, *z, *t1, *t2;
    int *idx, *nidx;
    double *sumB, *sqsB;
    cudaGetSymbolAddress((void**)&h0,   g_h0);
    cudaGetSymbolAddress((void**)&h1,   g_h1);
    cudaGetSymbolAddress((void**)&h2,   g_h2);
    cudaGetSymbolAddress((void**)&h3,   g_h3);
    cudaGetSymbolAddress((void**)&h4,   g_h4);
    cudaGetSymbolAddress((void**)&p1,   g_p1);
    cudaGetSymbolAddress((void**)&p2,   g_p2);
    cudaGetSymbolAddress((void**)&p3,   g_p3);
    cudaGetSymbolAddress((void**)&p4,   g_p4);
    cudaGetSymbolAddress((void**)&gmax, g_gmax);
    cudaGetSymbolAddress((void**)&z,    g_z);
    cudaGetSymbolAddress((void**)&t1,   g_t1);
    cudaGetSymbolAddress((void**)&t2,   g_t2);
    cudaGetSymbolAddress((void**)&idx,  g_idx);
    cudaGetSymbolAddress((void**)&nidx, g_nidx);
    cudaGetSymbolAddress((void**)&sumB, g_sum);
    cudaGetSymbolAddress((void**)&sqsB, g_sqs);

    const float* pin[4]  = {x,  p1, p2, p3};
    float*       pout[4] = {p1, p2, p3, p4};
    const float* hin[4]  = {h0, h1, h2, h3};
    float*       hout[4] = {h1, h2, h3, h4};
    const int    Ns[4]   = {4096, 1024, 256, 64};
    const int    Ms[4]   = {1024, 256, 64, 16};
    const int    Cin_[4] = {32, 64, 128, 256};
    const int    Cout_[4]= {64, 128, 256, 512};
    int nidxOff[4]; nidxOff[0] = 0;
    for (int s = 1; s < 4; s++) nidxOff[s] = nidxOff[s-1] + BB * Ms[s-1] * 16;

    // fork
    cudaEventRecord(eRoot, 0);
    cudaStreamWaitEvent(sF, eRoot, 0);
    cudaStreamWaitEvent(sK, eRoot, 0);

    // sF: FPS chain (writes idx + p_out directly)
    for (int s = 0; s < 4; s++) {
        run_fps(pin[s], idx, pout[s], Ns[s], sF);
        cudaEventRecord(eG[s], sF);
    }
    cudaEventRecord(eF, sF);

    // sK: kNN per stage
    for (int s = 0; s < 4; s++) {
        cudaStreamWaitEvent(sK, eG[s], 0);
        run_knn(pin[s], pout[s], Ns[s], Ms[s], nidx + nidxOff[s], sK);
        cudaEventRecord(eK[s], sK);
    }

    // main: stats zero + stage 0 (concurrent with FPS)
    zero_all_kernel<<<10,256>>>();
    int tot0 = BB*4096*32;
    lin0_kernel<<<(tot0+255)/256,256>>>(x, W1, h0);
    { dim3 sb(32, 32); stats_kernel<<<128, sb>>>(h0, BB*4096, 32, sumB, sqsB); }
    bnrelu32_kernel<<<(tot0+255)/256,256>>>(h0, tot0, sumB, sqsB, g1, b1, 1.0/(double)(BB*4096));

    // main: GEMM + BN chain
    for (int s = 0; s < 4; s++) {
        cudaStreamWaitEvent(0, eK[s], 0);
        int rows = BB * Ms[s] * 16;
        dim3 gg(rows/64, Cout_[s]/64);
        gemmF_kernel<<<gg, 256>>>(pin[s], hin[s], pout[s], nidx + nidxOff[s],
                                  Ws[s], gmax, Ns[s], Ms[s], Cin_[s], Cout_[s],
                                  sumB + (s+1)*512, sqsB + (s+1)*512);
        int bm = BB * Ms[s];
        bnapply_kernel<<<(bm*Cout_[s]+255)/256,256>>>(gmax, hout[s], bm*Cout_[s], Cout_[s],
                                                      sumB + (s+1)*512, sqsB + (s+1)*512,
                                                      gs[s], bs[s], 1.0/(double)rows);
    }
    cudaStreamWaitEvent(0, eF, 0);

    // head
    mean_kernel<<<(BB*512+255)/256,256>>>(h4);
    head_kernel<<<1,256>>>(z,  Wc1, bc1, gc1, hc1, t1, 512, 256, 1);
    head_kernel<<<1,128>>>(t1, Wc2, bc2, gc2, hc2, t2, 256, 128, 1);
    head_kernel<<<1, 64>>>(t2, Wc3, bc3, (const float*)0, (const float*)0, out, 128, 40, 0);
}